// round 6
// baseline (speedup 1.0000x reference)
#include <cuda_runtime.h>
#include <cuda_bf16.h>
#include <cstdint>

constexpr int B_ = 4;
constexpr int N_ = 16384;
constexpr int C_ = 128;
constexpr int M_ = 1024;
constexpr int K_ = 32;
constexpr int NCOL = B_ * M_ * K_;        // 131072
constexpr int NCB = NCOL / 128;           // 1024 column blocks
constexpr int NQ = B_ * M_;               // 4096 query groups
constexpr float RADIUS2 = 0.4f * 0.4f;
constexpr float EPS_ = 1e-5f;

// Scratch (device globals; no allocations allowed)
__device__ float g_Y1[128 * NCOL];
__device__ float g_Y2[128 * NCOL];
__device__ int   g_idx[NQ * K_];
__device__ float g_scale[3][256];
__device__ float g_shift[3][256];
__device__ float g_psum[256][NCB];
__device__ float g_psum2[256][NCB];
__device__ float g_max[256][NQ];
__device__ float g_min[256][NQ];

__device__ __forceinline__ float to_tf32(float x) {
    float r;
    asm("cvt.rna.tf32.f32 %0, %1;" : "=f"(r) : "f"(x));
    return r;
}

__device__ __forceinline__ void mma_tf32(float* d, float4 a, float2 b) {
    asm volatile(
        "mma.sync.aligned.m16n8k8.row.col.f32.tf32.tf32.f32 "
        "{%0,%1,%2,%3}, {%4,%5,%6,%7}, {%8,%9}, {%0,%1,%2,%3};"
        : "+f"(d[0]), "+f"(d[1]), "+f"(d[2]), "+f"(d[3])
        : "r"(__float_as_uint(a.x)), "r"(__float_as_uint(a.y)),
          "r"(__float_as_uint(a.z)), "r"(__float_as_uint(a.w)),
          "r"(__float_as_uint(b.x)), "r"(__float_as_uint(b.y)));
}

// ---------------------------------------------------------------------------
// Kernel 1: ball query (one warp per query) + write new_xyz to output
// ---------------------------------------------------------------------------
__global__ void ballquery_kernel(const float* __restrict__ xyz,
                                 const int* __restrict__ indices,
                                 float* __restrict__ out_newxyz) {
    int gwarp = (blockIdx.x * blockDim.x + threadIdx.x) >> 5;
    int lane = threadIdx.x & 31;
    int w = threadIdx.x >> 5;
    if (gwarp >= NQ) return;
    int b = gwarp / M_;
    int m = gwarp % M_;

    const float* base = xyz + (size_t)b * N_ * 3;
    int center = indices[b * M_ + m];
    float qx = base[center * 3 + 0];
    float qy = base[center * 3 + 1];
    float qz = base[center * 3 + 2];
    if (lane < 3) out_newxyz[(size_t)gwarp * 3 + lane] = base[center * 3 + lane];

    __shared__ int sidx[4][K_];
    int cnt = 0;
    for (int bn = 0; bn < N_ && cnt < K_; bn += 32) {
        int n = bn + lane;
        float dx = base[n * 3 + 0] - qx;
        float dy = base[n * 3 + 1] - qy;
        float dz = base[n * 3 + 2] - qz;
        float d2 = fmaf(dx, dx, fmaf(dy, dy, dz * dz));
        bool within = d2 < RADIUS2;
        unsigned mask = __ballot_sync(0xffffffffu, within);
        int pos = cnt + __popc(mask & ((1u << lane) - 1u));
        if (within && pos < K_) sidx[w][pos] = n;
        cnt += __popc(mask);
    }
    __syncwarp();
    if (cnt > K_) cnt = K_;
    int first = (cnt > 0) ? sidx[w][0] : 0;
    if (lane < K_) {
        int v = (lane < cnt) ? sidx[w][lane] : first;
        g_idx[(size_t)gwarp * K_ + lane] = v;
    }
}

// ---------------------------------------------------------------------------
// tf32 mma.sync GEMM: Y[Cout, NCOL] = W[Cout,Cin] * f(X[Cin,NCOL]) + bias
// MODE 0: conv1 — B tile gathered on the fly (xyz diff + features), write Y
// MODE 1: conv2 — B from Xin with BN(layer LIN)+ReLU, write Y
// MODE 2: conv3 — B from Xin with BN+ReLU; no Y write; fused max/min over K
// CTA: 128x128 tile, 256 threads, 8 warps (2x4), warp tile 64x32, BK=16.
// Fragment-native smem layout: A-frag = LDS.128, B-frag = LDS.64.
// ---------------------------------------------------------------------------
struct GSmem {
    float afrag[2][8][2][32][4];   // [buf][mtile][kstep][lane][reg]
    float bfrag[2][16][2][32][2];  // [buf][ntile][kstep][lane][reg]
    float sred[128][4];
    float qred[128][4];
    int   off[128];                // b*C*N + n  (feature gather base)
    int   pt[128];                 // b*N + n    (xyz gather base)
    float snew[128][3];
};

template <int MODE, int CIN, int LIN>
__global__ void __launch_bounds__(256)
mma_gemm_kernel(const float* __restrict__ W, const float* __restrict__ bias,
                const float* __restrict__ Xin,
                const float* __restrict__ xyz, const float* __restrict__ feat,
                const float* __restrict__ newxyz,
                float* __restrict__ Y) {
    __shared__ GSmem s;
    constexpr int NCH = (CIN + 15) / 16;

    const int tid = threadIdx.x;
    const int lane = tid & 31;
    const int wid = tid >> 5;
    const int wr = wid >> 2;     // 0..1
    const int wc = wid & 3;      // 0..3
    const int col0 = blockIdx.x * 128;
    const int row0 = blockIdx.y * 128;

    if (MODE == 0) {
        if (tid < 128) {
            int col = col0 + tid;
            int q = col >> 5;
            int b = q >> 10;
            int n = g_idx[col];
            s.off[tid] = b * C_ * N_ + n;
            s.pt[tid] = b * N_ + n;
            #pragma unroll
            for (int d = 0; d < 3; d++) s.snew[tid][d] = newxyz[q * 3 + d];
        }
        __syncthreads();
    }

    float rA[8], rB[8];

    auto ldgA = [&](int t) {
        int kc0 = t * 16;
        #pragma unroll
        for (int i = 0; i < 8; i++) {
            int e = i * 256 + tid;
            int k = e & 15;
            int m = e >> 4;
            int kc = kc0 + k;
            float v = (kc < CIN) ? W[(size_t)(row0 + m) * CIN + kc] : 0.f;
            rA[i] = to_tf32(v);
        }
    };
    auto ldgB = [&](int t) {
        int kc0 = t * 16;
        #pragma unroll
        for (int i = 0; i < 8; i++) {
            int e = i * 256 + tid;
            int c = e & 127;
            int k = e >> 7;
            int kc = kc0 + k;
            float v = 0.f;
            if (MODE == 0) {
                if (kc < 3) v = xyz[s.pt[c] * 3 + kc] - s.snew[c][kc];
                else if (kc < CIN) v = feat[(size_t)s.off[c] + (kc - 3) * N_];
            } else {
                v = Xin[(size_t)kc * NCOL + col0 + c];
                v = fmaxf(fmaf(v, g_scale[LIN][kc], g_shift[LIN][kc]), 0.f);
            }
            rB[i] = to_tf32(v);
        }
    };
    auto stsA = [&](int buf) {
        #pragma unroll
        for (int i = 0; i < 8; i++) {
            int e = i * 256 + tid;
            int k = e & 15;
            int m = e >> 4;
            s.afrag[buf][m >> 4][k >> 3][((m & 7) << 2) | (k & 3)]
                   [((m >> 3) & 1) | (((k >> 2) & 1) << 1)] = rA[i];
        }
    };
    auto stsB = [&](int buf) {
        #pragma unroll
        for (int i = 0; i < 8; i++) {
            int e = i * 256 + tid;
            int c = e & 127;
            int k = e >> 7;
            s.bfrag[buf][c >> 3][k >> 3][((c & 7) << 2) | (k & 3)][(k >> 2) & 1] = rB[i];
        }
    };

    float acc[4][4][4] = {};

    ldgA(0); ldgB(0);
    stsA(0); stsB(0);
    __syncthreads();

    for (int t = 0; t < NCH; t++) {
        if (t + 1 < NCH) { ldgA(t + 1); ldgB(t + 1); }
        int buf = t & 1;
        #pragma unroll
        for (int ks = 0; ks < 2; ks++) {
            float4 av[4];
            float2 bv[4];
            #pragma unroll
            for (int mt = 0; mt < 4; mt++)
                av[mt] = *reinterpret_cast<const float4*>(&s.afrag[buf][wr * 4 + mt][ks][lane][0]);
            #pragma unroll
            for (int nt = 0; nt < 4; nt++)
                bv[nt] = *reinterpret_cast<const float2*>(&s.bfrag[buf][wc * 4 + nt][ks][lane][0]);
            #pragma unroll
            for (int mt = 0; mt < 4; mt++)
                #pragma unroll
                for (int nt = 0; nt < 4; nt++)
                    mma_tf32(acc[mt][nt], av[mt], bv[nt]);
        }
        if (t + 1 < NCH) { stsA(buf ^ 1); stsB(buf ^ 1); }
        __syncthreads();
    }

    // ---- epilogue ----
    const int rq = lane >> 2;       // quad row
    const int qc = lane & 3;        // quad col
    #pragma unroll
    for (int mt = 0; mt < 4; mt++) {
        int rA_ = wr * 64 + mt * 16 + rq;
        int rB_ = rA_ + 8;
        float bA = bias[row0 + rA_];
        float bB = bias[row0 + rB_];
        float sA = 0.f, qA = 0.f, sB = 0.f, qB = 0.f;
        float mxA = -3.4e38f, mnA = 3.4e38f, mxB = -3.4e38f, mnB = 3.4e38f;
        #pragma unroll
        for (int nt = 0; nt < 4; nt++) {
            float c0 = acc[mt][nt][0] + bA;
            float c1 = acc[mt][nt][1] + bA;
            float c2 = acc[mt][nt][2] + bB;
            float c3 = acc[mt][nt][3] + bB;
            sA += c0 + c1; qA += c0 * c0 + c1 * c1;
            sB += c2 + c3; qB += c2 * c2 + c3 * c3;
            if (MODE == 2) {
                mxA = fmaxf(mxA, fmaxf(c0, c1)); mnA = fminf(mnA, fminf(c0, c1));
                mxB = fmaxf(mxB, fmaxf(c2, c3)); mnB = fminf(mnB, fminf(c2, c3));
            } else {
                size_t cidx = (size_t)col0 + wc * 32 + nt * 8 + qc * 2;
                *reinterpret_cast<float2*>(&Y[(size_t)(row0 + rA_) * NCOL + cidx]) =
                    make_float2(c0, c1);
                *reinterpret_cast<float2*>(&Y[(size_t)(row0 + rB_) * NCOL + cidx]) =
                    make_float2(c2, c3);
            }
        }
        #pragma unroll
        for (int msk = 1; msk <= 2; msk <<= 1) {
            sA += __shfl_xor_sync(0xffffffffu, sA, msk);
            qA += __shfl_xor_sync(0xffffffffu, qA, msk);
            sB += __shfl_xor_sync(0xffffffffu, sB, msk);
            qB += __shfl_xor_sync(0xffffffffu, qB, msk);
            if (MODE == 2) {
                mxA = fmaxf(mxA, __shfl_xor_sync(0xffffffffu, mxA, msk));
                mnA = fminf(mnA, __shfl_xor_sync(0xffffffffu, mnA, msk));
                mxB = fmaxf(mxB, __shfl_xor_sync(0xffffffffu, mxB, msk));
                mnB = fminf(mnB, __shfl_xor_sync(0xffffffffu, mnB, msk));
            }
        }
        if (qc == 0) {
            s.sred[rA_][wc] = sA; s.qred[rA_][wc] = qA;
            s.sred[rB_][wc] = sB; s.qred[rB_][wc] = qB;
            if (MODE == 2) {
                int mg = blockIdx.x * 4 + wc;      // query-group index
                g_max[row0 + rA_][mg] = mxA; g_min[row0 + rA_][mg] = mnA;
                g_max[row0 + rB_][mg] = mxB; g_min[row0 + rB_][mg] = mnB;
            }
        }
    }
    __syncthreads();
    if (tid < 128) {
        float ss = s.sred[tid][0] + s.sred[tid][1] + s.sred[tid][2] + s.sred[tid][3];
        float qq = s.qred[tid][0] + s.qred[tid][1] + s.qred[tid][2] + s.qred[tid][3];
        g_psum[row0 + tid][blockIdx.x] = ss;
        g_psum2[row0 + tid][blockIdx.x] = qq;
    }
}

// ---------------------------------------------------------------------------
// finalize BN stats from partials -> folded scale/shift
// ---------------------------------------------------------------------------
__global__ void finalize_kernel(const float* __restrict__ gamma,
                                const float* __restrict__ beta, int layer) {
    int c = blockIdx.x;
    double s = 0.0, s2 = 0.0;
    for (int j = threadIdx.x; j < NCB; j += 256) {
        s += (double)g_psum[c][j];
        s2 += (double)g_psum2[c][j];
    }
    #pragma unroll
    for (int o = 16; o > 0; o >>= 1) {
        s += __shfl_down_sync(0xffffffffu, s, o);
        s2 += __shfl_down_sync(0xffffffffu, s2, o);
    }
    __shared__ double ws[8], ws2[8];
    int w = threadIdx.x >> 5, lane = threadIdx.x & 31;
    if (lane == 0) { ws[w] = s; ws2[w] = s2; }
    __syncthreads();
    if (threadIdx.x == 0) {
        double S = 0.0, S2 = 0.0;
        #pragma unroll
        for (int i = 0; i < 8; i++) { S += ws[i]; S2 += ws2[i]; }
        double mean = S / NCOL;
        float var = (float)(S2 / NCOL - mean * mean);
        float inv = rsqrtf(var + EPS_);
        float sc = gamma[c] * inv;
        g_scale[layer][c] = sc;
        g_shift[layer][c] = beta[c] - (float)mean * sc;
    }
}

// ---------------------------------------------------------------------------
// BN3 + ReLU over fused max/min -> new_features (B, 256, M)
// ---------------------------------------------------------------------------
__global__ void maxpool_kernel(float* __restrict__ out) {
    int idx = blockIdx.x * blockDim.x + threadIdx.x;   // 256*4096 total
    int q = idx & (NQ - 1);
    int c = idx >> 12;
    float sc = g_scale[2][c];
    float sh = g_shift[2][c];
    float v = (sc >= 0.f) ? g_max[c][q] : g_min[c][q];
    float r = fmaxf(fmaf(v, sc, sh), 0.f);
    int b = q >> 10;
    int m = q & 1023;
    out[12288 + ((size_t)b * 256 + c) * M_ + m] = r;
}

// ---------------------------------------------------------------------------
extern "C" void kernel_launch(void* const* d_in, const int* in_sizes, int n_in,
                              void* d_out, int out_size) {
    const float* xyz  = (const float*)d_in[0];
    const float* feat = (const float*)d_in[1];
    const int* indices = (const int*)d_in[2];
    const float* w1 = (const float*)d_in[3];
    const float* b1 = (const float*)d_in[4];
    const float* g1 = (const float*)d_in[5];
    const float* be1 = (const float*)d_in[6];
    const float* w2 = (const float*)d_in[7];
    const float* b2 = (const float*)d_in[8];
    const float* g2 = (const float*)d_in[9];
    const float* be2 = (const float*)d_in[10];
    const float* w3 = (const float*)d_in[11];
    const float* b3 = (const float*)d_in[12];
    const float* g3 = (const float*)d_in[13];
    const float* be3 = (const float*)d_in[14];
    float* out = (float*)d_out;

    ballquery_kernel<<<NQ / 4, 128>>>(xyz, indices, out);

    // conv1: 131 -> 128, gather fused into B loader
    mma_gemm_kernel<0, 131, 0><<<dim3(NCB, 1), 256>>>(
        w1, b1, nullptr, xyz, feat, out, g_Y1);
    finalize_kernel<<<128, 256>>>(g1, be1, 0);
    // conv2: 128 -> 128 (BN1+ReLU on load)
    mma_gemm_kernel<1, 128, 0><<<dim3(NCB, 1), 256>>>(
        w2, b2, g_Y1, nullptr, nullptr, nullptr, g_Y2);
    finalize_kernel<<<128, 256>>>(g2, be2, 1);
    // conv3: 128 -> 256 (BN2+ReLU on load), fused max/min, no Y write
    mma_gemm_kernel<2, 128, 1><<<dim3(NCB, 2), 256>>>(
        w3, b3, g_Y2, nullptr, nullptr, nullptr, nullptr);
    finalize_kernel<<<256, 256>>>(g3, be3, 2);
    // BN3 + ReLU applied to max/min
    maxpool_kernel<<<(256 * NQ) / 256, 256>>>(out);
}

// round 10
// speedup vs baseline: 1.9542x; 1.9542x over previous
#include <cuda_runtime.h>
#include <cuda_bf16.h>
#include <cstdint>

constexpr int B_ = 4;
constexpr int N_ = 16384;
constexpr int C_ = 128;
constexpr int M_ = 1024;
constexpr int K_ = 32;
constexpr int NCOL = B_ * M_ * K_;        // 131072
constexpr int NCB = NCOL / 128;           // 1024 column blocks
constexpr int NQ = B_ * M_;               // 4096 query groups
constexpr float RADIUS2 = 0.4f * 0.4f;
constexpr float EPS_ = 1e-5f;

// Scratch (device globals; no allocations allowed)
__device__ float g_Y1[128 * NCOL];
__device__ float g_Y2[128 * NCOL];
__device__ int   g_idx[NQ * K_];
__device__ float g_scale[3][256];
__device__ float g_shift[3][256];
__device__ float g_psum[256][NCB];
__device__ float g_psum2[256][NCB];
__device__ float g_max[256][NQ];
__device__ float g_min[256][NQ];

// ---------------------------------------------------------------------------
// Kernel 1: ball query (one warp per query) + write new_xyz to output
// ---------------------------------------------------------------------------
__global__ void ballquery_kernel(const float* __restrict__ xyz,
                                 const int* __restrict__ indices,
                                 float* __restrict__ out_newxyz) {
    int gwarp = (blockIdx.x * blockDim.x + threadIdx.x) >> 5;
    int lane = threadIdx.x & 31;
    int w = threadIdx.x >> 5;
    if (gwarp >= NQ) return;
    int b = gwarp / M_;
    int m = gwarp % M_;

    const float* base = xyz + (size_t)b * N_ * 3;
    int center = indices[b * M_ + m];
    float qx = base[center * 3 + 0];
    float qy = base[center * 3 + 1];
    float qz = base[center * 3 + 2];
    if (lane < 3) out_newxyz[(size_t)gwarp * 3 + lane] = base[center * 3 + lane];

    __shared__ int sidx[4][K_];
    int cnt = 0;
    for (int bn = 0; bn < N_ && cnt < K_; bn += 32) {
        int n = bn + lane;
        float dx = base[n * 3 + 0] - qx;
        float dy = base[n * 3 + 1] - qy;
        float dz = base[n * 3 + 2] - qz;
        float d2 = fmaf(dx, dx, fmaf(dy, dy, dz * dz));
        bool within = d2 < RADIUS2;
        unsigned mask = __ballot_sync(0xffffffffu, within);
        int pos = cnt + __popc(mask & ((1u << lane) - 1u));
        if (within && pos < K_) sidx[w][pos] = n;
        cnt += __popc(mask);
    }
    __syncwarp();
    if (cnt > K_) cnt = K_;
    int first = (cnt > 0) ? sidx[w][0] : 0;
    if (lane < K_) {
        int v = (lane < cnt) ? sidx[w][lane] : first;
        g_idx[(size_t)gwarp * K_ + lane] = v;
    }
}

// ---------------------------------------------------------------------------
// FFMA GEMM: Y[Cout, NCOL] = W[Cout,Cin] * f(X[Cin,NCOL]) + bias
// MODE 0: conv1 — B gathered on the fly (xyz diff + features), write Y
// MODE 1: conv2 — B from Xin with BN(LIN)+ReLU, write Y
// MODE 2: conv3 — B from Xin with BN+ReLU; no Y; fused max/min over K-groups
// 128x128 tile, BK=16, 256 threads, 8x8 microtile (4+4 split both dims),
// double-buffered smem, k-major layout (all frag reads LDS.128).
// Fused per-row stats partials (register/shuffle only).
// ---------------------------------------------------------------------------
template <int MODE, int CIN, int LIN>
__global__ void __launch_bounds__(256)
gemm_kernel(const float* __restrict__ W, const float* __restrict__ bias,
            const float* __restrict__ Xin,
            const float* __restrict__ xyz, const float* __restrict__ feat,
            const float* __restrict__ newxyz,
            float* __restrict__ Y) {
    constexpr int BK = 16;
    constexpr int NCH = (CIN + BK - 1) / BK;

    __shared__ float As[2][BK][132];   // padded: STS 2-way max, LDS.128-aligned
    __shared__ float Bs[2][BK][128];
    __shared__ int   s_off[MODE == 0 ? 128 : 1];
    __shared__ int   s_pt[MODE == 0 ? 128 : 1];
    __shared__ float s_new[MODE == 0 ? 128 : 1][3];

    const int tid = threadIdx.x;
    const int tx = tid & 15;
    const int ty = tid >> 4;
    const int col0 = blockIdx.x * 128;
    const int row0 = blockIdx.y * 128;

    if (MODE == 0) {
        if (tid < 128) {
            int col = col0 + tid;
            int q = col >> 5;
            int b = q >> 10;
            int n = g_idx[col];
            s_off[tid] = b * C_ * N_ + n;
            s_pt[tid] = b * N_ + n;
            #pragma unroll
            for (int d = 0; d < 3; d++) s_new[tid][d] = newxyz[q * 3 + d];
        }
        __syncthreads();
    }

    float aR[8];
    float bRs[8];        // MODE 0 scalar staging
    float4 bR4[2];       // MODE 1/2 vector staging

    auto ldgA = [&](int t) {
        int kc0 = t * BK;
        #pragma unroll
        for (int i = 0; i < 8; i++) {
            int e = i * 256 + tid;
            int k = e & 15;
            int m = e >> 4;
            int kc = kc0 + k;
            aR[i] = (kc < CIN) ? W[(size_t)(row0 + m) * CIN + kc] : 0.f;
        }
    };
    auto stsA = [&](int buf) {
        #pragma unroll
        for (int i = 0; i < 8; i++) {
            int e = i * 256 + tid;
            As[buf][e & 15][e >> 4] = aR[i];
        }
    };
    auto ldgB = [&](int t) {
        int kc0 = t * BK;
        if (MODE == 0) {
            #pragma unroll
            for (int i = 0; i < 8; i++) {
                int e = i * 256 + tid;
                int c = e & 127;
                int kc = kc0 + (e >> 7);
                float v = 0.f;
                if (kc < 3) v = xyz[s_pt[c] * 3 + kc] - s_new[c][kc];
                else if (kc < CIN) v = feat[(size_t)s_off[c] + (kc - 3) * N_];
                bRs[i] = v;
            }
        } else {
            #pragma unroll
            for (int i = 0; i < 2; i++) {
                int f = i * 256 + tid;
                int c4 = f & 31;
                int kc = kc0 + (f >> 5);
                float4 v = *reinterpret_cast<const float4*>(
                    &Xin[(size_t)kc * NCOL + col0 + c4 * 4]);
                float sc = g_scale[LIN][kc];
                float sh = g_shift[LIN][kc];
                v.x = fmaxf(fmaf(v.x, sc, sh), 0.f);
                v.y = fmaxf(fmaf(v.y, sc, sh), 0.f);
                v.z = fmaxf(fmaf(v.z, sc, sh), 0.f);
                v.w = fmaxf(fmaf(v.w, sc, sh), 0.f);
                bR4[i] = v;
            }
        }
    };
    auto stsB = [&](int buf) {
        if (MODE == 0) {
            #pragma unroll
            for (int i = 0; i < 8; i++) {
                int e = i * 256 + tid;
                Bs[buf][e >> 7][e & 127] = bRs[i];
            }
        } else {
            #pragma unroll
            for (int i = 0; i < 2; i++) {
                int f = i * 256 + tid;
                *reinterpret_cast<float4*>(&Bs[buf][f >> 5][(f & 31) * 4]) = bR4[i];
            }
        }
    };

    float acc[8][8] = {};   // u: rows ty*4+{0..3}, 64+ty*4+{0..3}; v: cols tx*4..., 64+tx*4...

    ldgA(0); ldgB(0);
    stsA(0); stsB(0);
    __syncthreads();

    for (int t = 0; t < NCH; t++) {
        if (t + 1 < NCH) { ldgA(t + 1); ldgB(t + 1); }
        int buf = t & 1;
        #pragma unroll
        for (int kk = 0; kk < BK; kk++) {
            float4 a0 = *reinterpret_cast<const float4*>(&As[buf][kk][ty * 4]);
            float4 a1 = *reinterpret_cast<const float4*>(&As[buf][kk][64 + ty * 4]);
            float4 b0 = *reinterpret_cast<const float4*>(&Bs[buf][kk][tx * 4]);
            float4 b1 = *reinterpret_cast<const float4*>(&Bs[buf][kk][64 + tx * 4]);
            float a[8] = {a0.x, a0.y, a0.z, a0.w, a1.x, a1.y, a1.z, a1.w};
            float b[8] = {b0.x, b0.y, b0.z, b0.w, b1.x, b1.y, b1.z, b1.w};
            #pragma unroll
            for (int u = 0; u < 8; u++)
                #pragma unroll
                for (int v = 0; v < 8; v++)
                    acc[u][v] = fmaf(a[u], b[v], acc[u][v]);
        }
        if (t + 1 < NCH) { stsA(buf ^ 1); stsB(buf ^ 1); }
        __syncthreads();
    }

    // ---- epilogue: bias, Y store (or max/min), stats via shuffles ----
    #pragma unroll
    for (int u = 0; u < 8; u++) {
        int r = (u < 4) ? (ty * 4 + u) : (64 + ty * 4 + (u - 4));
        float bv = bias[row0 + r];
        float c_[8];
        #pragma unroll
        for (int v = 0; v < 8; v++) c_[v] = acc[u][v] + bv;

        float rs = 0.f, rq = 0.f;
        #pragma unroll
        for (int v = 0; v < 8; v++) { rs += c_[v]; rq += c_[v] * c_[v]; }
        #pragma unroll
        for (int msk = 1; msk <= 8; msk <<= 1) {
            rs += __shfl_xor_sync(0xffffffffu, rs, msk);
            rq += __shfl_xor_sync(0xffffffffu, rq, msk);
        }
        if (tx == 0) {
            g_psum[row0 + r][blockIdx.x] = rs;
            g_psum2[row0 + r][blockIdx.x] = rq;
        }

        if (MODE == 2) {
            // cols tx*4+v (v<4) -> group tx>>3; cols 64+tx*4 -> group 2+(tx>>3)
            float mxA = fmaxf(fmaxf(c_[0], c_[1]), fmaxf(c_[2], c_[3]));
            float mnA = fminf(fminf(c_[0], c_[1]), fminf(c_[2], c_[3]));
            float mxB = fmaxf(fmaxf(c_[4], c_[5]), fmaxf(c_[6], c_[7]));
            float mnB = fminf(fminf(c_[4], c_[5]), fminf(c_[6], c_[7]));
            #pragma unroll
            for (int msk = 1; msk <= 4; msk <<= 1) {
                mxA = fmaxf(mxA, __shfl_xor_sync(0xffffffffu, mxA, msk));
                mnA = fminf(mnA, __shfl_xor_sync(0xffffffffu, mnA, msk));
                mxB = fmaxf(mxB, __shfl_xor_sync(0xffffffffu, mxB, msk));
                mnB = fminf(mnB, __shfl_xor_sync(0xffffffffu, mnB, msk));
            }
            if ((tx & 7) == 0) {
                int gbase = blockIdx.x * 4;
                int gA = gbase + (tx >> 3);
                int gB = gbase + 2 + (tx >> 3);
                g_max[row0 + r][gA] = mxA; g_min[row0 + r][gA] = mnA;
                g_max[row0 + r][gB] = mxB; g_min[row0 + r][gB] = mnB;
            }
        } else {
            float* yr = &Y[(size_t)(row0 + r) * NCOL + col0];
            *reinterpret_cast<float4*>(&yr[tx * 4]) =
                make_float4(c_[0], c_[1], c_[2], c_[3]);
            *reinterpret_cast<float4*>(&yr[64 + tx * 4]) =
                make_float4(c_[4], c_[5], c_[6], c_[7]);
        }
    }
}

// ---------------------------------------------------------------------------
// finalize BN stats from partials -> folded scale/shift
// ---------------------------------------------------------------------------
__global__ void finalize_kernel(const float* __restrict__ gamma,
                                const float* __restrict__ beta, int layer) {
    int c = blockIdx.x;
    double s = 0.0, s2 = 0.0;
    for (int j = threadIdx.x; j < NCB; j += 256) {
        s += (double)g_psum[c][j];
        s2 += (double)g_psum2[c][j];
    }
    #pragma unroll
    for (int o = 16; o > 0; o >>= 1) {
        s += __shfl_down_sync(0xffffffffu, s, o);
        s2 += __shfl_down_sync(0xffffffffu, s2, o);
    }
    __shared__ double ws[8], ws2[8];
    int w = threadIdx.x >> 5, lane = threadIdx.x & 31;
    if (lane == 0) { ws[w] = s; ws2[w] = s2; }
    __syncthreads();
    if (threadIdx.x == 0) {
        double S = 0.0, S2 = 0.0;
        #pragma unroll
        for (int i = 0; i < 8; i++) { S += ws[i]; S2 += ws2[i]; }
        double mean = S / NCOL;
        float var = (float)(S2 / NCOL - mean * mean);
        float inv = rsqrtf(var + EPS_);
        float sc = gamma[c] * inv;
        g_scale[layer][c] = sc;
        g_shift[layer][c] = beta[c] - (float)mean * sc;
    }
}

// ---------------------------------------------------------------------------
// BN3 + ReLU over fused max/min -> new_features (B, 256, M)
// ---------------------------------------------------------------------------
__global__ void maxpool_kernel(float* __restrict__ out) {
    int idx = blockIdx.x * blockDim.x + threadIdx.x;   // 256*4096 total
    int q = idx & (NQ - 1);
    int c = idx >> 12;
    float sc = g_scale[2][c];
    float sh = g_shift[2][c];
    float v = (sc >= 0.f) ? g_max[c][q] : g_min[c][q];
    float r = fmaxf(fmaf(v, sc, sh), 0.f);
    int b = q >> 10;
    int m = q & 1023;
    out[12288 + ((size_t)b * 256 + c) * M_ + m] = r;
}

// ---------------------------------------------------------------------------
extern "C" void kernel_launch(void* const* d_in, const int* in_sizes, int n_in,
                              void* d_out, int out_size) {
    const float* xyz  = (const float*)d_in[0];
    const float* feat = (const float*)d_in[1];
    const int* indices = (const int*)d_in[2];
    const float* w1 = (const float*)d_in[3];
    const float* b1 = (const float*)d_in[4];
    const float* g1 = (const float*)d_in[5];
    const float* be1 = (const float*)d_in[6];
    const float* w2 = (const float*)d_in[7];
    const float* b2 = (const float*)d_in[8];
    const float* g2 = (const float*)d_in[9];
    const float* be2 = (const float*)d_in[10];
    const float* w3 = (const float*)d_in[11];
    const float* b3 = (const float*)d_in[12];
    const float* g3 = (const float*)d_in[13];
    const float* be3 = (const float*)d_in[14];
    float* out = (float*)d_out;

    ballquery_kernel<<<NQ / 4, 128>>>(xyz, indices, out);

    // conv1: 131 -> 128, gather fused into B loader
    gemm_kernel<0, 131, 0><<<dim3(NCB, 1), 256>>>(
        w1, b1, nullptr, xyz, feat, out, g_Y1);
    finalize_kernel<<<128, 256>>>(g1, be1, 0);
    // conv2: 128 -> 128 (BN1+ReLU on load)
    gemm_kernel<1, 128, 0><<<dim3(NCB, 1), 256>>>(
        w2, b2, g_Y1, nullptr, nullptr, nullptr, g_Y2);
    finalize_kernel<<<128, 256>>>(g2, be2, 1);
    // conv3: 128 -> 256 (BN2+ReLU on load), fused max/min, no Y write
    gemm_kernel<2, 128, 1><<<dim3(NCB, 2), 256>>>(
        w3, b3, g_Y2, nullptr, nullptr, nullptr, nullptr);
    finalize_kernel<<<256, 256>>>(g3, be3, 2);
    // BN3 + ReLU applied to max/min
    maxpool_kernel<<<(256 * NQ) / 256, 256>>>(out);
}

// round 11
// speedup vs baseline: 1.9757x; 1.0110x over previous
#include <cuda_runtime.h>
#include <cuda_bf16.h>
#include <cstdint>

constexpr int B_ = 4;
constexpr int N_ = 16384;
constexpr int C_ = 128;
constexpr int M_ = 1024;
constexpr int K_ = 32;
constexpr int NCOL = B_ * M_ * K_;        // 131072
constexpr int NCB = NCOL / 128;           // 1024 column blocks
constexpr int NQ = B_ * M_;               // 4096 query groups
constexpr float RADIUS2 = 0.4f * 0.4f;
constexpr float EPS_ = 1e-5f;

// Scratch (device globals; no allocations allowed)
__device__ float g_Y1[128 * NCOL];
__device__ float g_Y2[128 * NCOL];
__device__ int   g_idx[NQ * K_];
__device__ float g_scale[3][256];
__device__ float g_shift[3][256];
__device__ float g_psum[256][NCB];
__device__ float g_psum2[256][NCB];
__device__ float g_max[256][NQ];
__device__ float g_min[256][NQ];

// ---------------------------------------------------------------------------
// Kernel 1: ball query (one warp per query) + write new_xyz to output
// ---------------------------------------------------------------------------
__global__ void ballquery_kernel(const float* __restrict__ xyz,
                                 const int* __restrict__ indices,
                                 float* __restrict__ out_newxyz) {
    int gwarp = (blockIdx.x * blockDim.x + threadIdx.x) >> 5;
    int lane = threadIdx.x & 31;
    int w = threadIdx.x >> 5;
    if (gwarp >= NQ) return;
    int b = gwarp / M_;
    int m = gwarp % M_;

    const float* base = xyz + (size_t)b * N_ * 3;
    int center = indices[b * M_ + m];
    float qx = base[center * 3 + 0];
    float qy = base[center * 3 + 1];
    float qz = base[center * 3 + 2];
    if (lane < 3) out_newxyz[(size_t)gwarp * 3 + lane] = base[center * 3 + lane];

    __shared__ int sidx[4][K_];
    int cnt = 0;
    for (int bn = 0; bn < N_ && cnt < K_; bn += 32) {
        int n = bn + lane;
        float dx = base[n * 3 + 0] - qx;
        float dy = base[n * 3 + 1] - qy;
        float dz = base[n * 3 + 2] - qz;
        float d2 = fmaf(dx, dx, fmaf(dy, dy, dz * dz));
        bool within = d2 < RADIUS2;
        unsigned mask = __ballot_sync(0xffffffffu, within);
        int pos = cnt + __popc(mask & ((1u << lane) - 1u));
        if (within && pos < K_) sidx[w][pos] = n;
        cnt += __popc(mask);
    }
    __syncwarp();
    if (cnt > K_) cnt = K_;
    int first = (cnt > 0) ? sidx[w][0] : 0;
    if (lane < K_) {
        int v = (lane < cnt) ? sidx[w][lane] : first;
        g_idx[(size_t)gwarp * K_ + lane] = v;
    }
}

// ---------------------------------------------------------------------------
// FFMA GEMM (R2-proven structure): Y = W * f(X) + bias, 128x128x16 tiles,
// double-buffered, Asm[rm][kk] layout (scalar broadcast A reads).
// MODE 0: conv1 — B gathered on the fly (xyz diff + features), write Y
// MODE 1: conv2 — B from Xin with BN(LIN)+ReLU, write Y
// MODE 2: conv3 — B from Xin with BN+ReLU; no Y; fused max/min over K-groups
// Fused per-row stats partials (register/shuffle only).
// ---------------------------------------------------------------------------
template <int MODE, int CIN, int LIN>
__global__ void __launch_bounds__(256)
gemm_kernel(const float* __restrict__ W, const float* __restrict__ bias,
            const float* __restrict__ Xin,
            const float* __restrict__ xyz, const float* __restrict__ feat,
            const float* __restrict__ newxyz,
            float* __restrict__ Y) {
    constexpr int BM = 128, BN = 128, BK = 16;
    constexpr int NCH = (CIN + BK - 1) / BK;
    __shared__ float Asm[2][BM][BK + 1];   // [rm][kk], padded
    __shared__ float Bsm[2][BK][BN];
    __shared__ int   s_off[MODE == 0 ? 128 : 1];
    __shared__ int   s_pt[MODE == 0 ? 128 : 1];
    __shared__ float s_new[MODE == 0 ? 128 : 1][3];

    float* Yp = Y;

    const int tid = threadIdx.x;
    const int tx = tid & 15;
    const int ty = tid >> 4;
    const int col0 = blockIdx.x * BN;
    const int row0 = blockIdx.y * BM;

    if (MODE == 0) {
        if (tid < 128) {
            int col = col0 + tid;
            int q = col >> 5;
            int b = q >> 10;
            int n = g_idx[col];
            s_off[tid] = b * C_ * N_ + n;
            s_pt[tid] = b * N_ + n;
            #pragma unroll
            for (int d = 0; d < 3; d++) s_new[tid][d] = newxyz[q * 3 + d];
        }
        __syncthreads();
    }

    float a_reg[8];
    float4 b_reg[2];
    float b_regs[8];

    auto loadA = [&](int t) {
        int kt = t * BK;
        #pragma unroll
        for (int i = 0; i < 8; i++) {
            int e = tid + i * 256;
            int kk = e & 15;
            int rm = e >> 4;
            int kc = kt + kk;
            a_reg[i] = (kc < CIN) ? W[(size_t)(row0 + rm) * CIN + kc] : 0.f;
        }
    };
    auto loadB = [&](int t) {
        int kt = t * BK;
        if (MODE == 0) {
            #pragma unroll
            for (int i = 0; i < 8; i++) {
                int e = tid + i * 256;
                int cn = e & 127;
                int kc = kt + (e >> 7);
                float v = 0.f;
                if (kc < 3) v = xyz[s_pt[cn] * 3 + kc] - s_new[cn][kc];
                else if (kc < CIN) v = feat[(size_t)s_off[cn] + (kc - 3) * N_];
                b_regs[i] = v;
            }
        } else {
            #pragma unroll
            for (int i = 0; i < 2; i++) {
                int f = tid + i * 256;
                int c4 = f & 31;
                int kk = f >> 5;
                int kc = kt + kk;
                float4 v = *reinterpret_cast<const float4*>(
                    &Xin[(size_t)kc * NCOL + col0 + c4 * 4]);
                float sc = g_scale[LIN][kc];
                float sh = g_shift[LIN][kc];
                v.x = fmaxf(fmaf(v.x, sc, sh), 0.f);
                v.y = fmaxf(fmaf(v.y, sc, sh), 0.f);
                v.z = fmaxf(fmaf(v.z, sc, sh), 0.f);
                v.w = fmaxf(fmaf(v.w, sc, sh), 0.f);
                b_reg[i] = v;
            }
        }
    };
    auto storeA = [&](int buf) {
        #pragma unroll
        for (int i = 0; i < 8; i++) {
            int e = tid + i * 256;
            int kk = e & 15;
            int rm = e >> 4;
            Asm[buf][rm][kk] = a_reg[i];
        }
    };
    auto storeB = [&](int buf) {
        if (MODE == 0) {
            #pragma unroll
            for (int i = 0; i < 8; i++) {
                int e = tid + i * 256;
                Bsm[buf][e >> 7][e & 127] = b_regs[i];
            }
        } else {
            #pragma unroll
            for (int i = 0; i < 2; i++) {
                int f = tid + i * 256;
                int c4 = f & 31;
                int kk = f >> 5;
                *reinterpret_cast<float4*>(&Bsm[buf][kk][c4 * 4]) = b_reg[i];
            }
        }
    };

    float acc[8][8] = {};   // rows: ri*64 + ty*4 + i; cols: tx*4..., 64+tx*4...

    loadA(0); loadB(0);
    storeA(0); storeB(0);
    __syncthreads();

    int buf = 0;
    for (int t = 0; t < NCH; t++) {
        if (t + 1 < NCH) { loadA(t + 1); loadB(t + 1); }
        #pragma unroll
        for (int kk = 0; kk < BK; kk++) {
            float a[8], b[8];
            #pragma unroll
            for (int i = 0; i < 4; i++) {
                a[i]     = Asm[buf][ty * 4 + i][kk];
                a[4 + i] = Asm[buf][64 + ty * 4 + i][kk];
            }
            float4 bv0 = *reinterpret_cast<const float4*>(&Bsm[buf][kk][tx * 4]);
            float4 bv1 = *reinterpret_cast<const float4*>(&Bsm[buf][kk][64 + tx * 4]);
            b[0] = bv0.x; b[1] = bv0.y; b[2] = bv0.z; b[3] = bv0.w;
            b[4] = bv1.x; b[5] = bv1.y; b[6] = bv1.z; b[7] = bv1.w;
            #pragma unroll
            for (int u = 0; u < 8; u++)
                #pragma unroll
                for (int v = 0; v < 8; v++)
                    acc[u][v] = fmaf(a[u], b[v], acc[u][v]);
        }
        if (t + 1 < NCH) { storeA(buf ^ 1); storeB(buf ^ 1); }
        __syncthreads();
        buf ^= 1;
    }

    // ---- epilogue: bias; Y store or max/min; stats via shuffles ----
    #pragma unroll
    for (int u = 0; u < 8; u++) {
        int ri = u >> 2, i = u & 3;
        int r = ri * 64 + ty * 4 + i;
        float bv = bias[row0 + r];
        float c_[8];
        #pragma unroll
        for (int v = 0; v < 8; v++) c_[v] = acc[u][v] + bv;

        float rs = 0.f, rq = 0.f;
        #pragma unroll
        for (int v = 0; v < 8; v++) { rs += c_[v]; rq += c_[v] * c_[v]; }
        #pragma unroll
        for (int msk = 8; msk > 0; msk >>= 1) {
            rs += __shfl_xor_sync(0xffffffffu, rs, msk);
            rq += __shfl_xor_sync(0xffffffffu, rq, msk);
        }
        if (tx == 0) {
            g_psum[row0 + r][blockIdx.x] = rs;
            g_psum2[row0 + r][blockIdx.x] = rq;
        }

        if (MODE == 2) {
            // cols tx*4+{0..3} -> K-group (tx>>3); cols 64+tx*4 -> group 2+(tx>>3)
            float mxA = fmaxf(fmaxf(c_[0], c_[1]), fmaxf(c_[2], c_[3]));
            float mnA = fminf(fminf(c_[0], c_[1]), fminf(c_[2], c_[3]));
            float mxB = fmaxf(fmaxf(c_[4], c_[5]), fmaxf(c_[6], c_[7]));
            float mnB = fminf(fminf(c_[4], c_[5]), fminf(c_[6], c_[7]));
            #pragma unroll
            for (int msk = 1; msk <= 4; msk <<= 1) {
                mxA = fmaxf(mxA, __shfl_xor_sync(0xffffffffu, mxA, msk));
                mnA = fminf(mnA, __shfl_xor_sync(0xffffffffu, mnA, msk));
                mxB = fmaxf(mxB, __shfl_xor_sync(0xffffffffu, mxB, msk));
                mnB = fminf(mnB, __shfl_xor_sync(0xffffffffu, mnB, msk));
            }
            if ((tx & 7) == 0) {
                int gbase = blockIdx.x * 4;
                int gA = gbase + (tx >> 3);
                int gB = gbase + 2 + (tx >> 3);
                g_max[row0 + r][gA] = mxA; g_min[row0 + r][gA] = mnA;
                g_max[row0 + r][gB] = mxB; g_min[row0 + r][gB] = mnB;
            }
        } else {
            float* yr = &Yp[(size_t)(row0 + r) * NCOL + col0];
            *reinterpret_cast<float4*>(&yr[tx * 4]) =
                make_float4(c_[0], c_[1], c_[2], c_[3]);
            *reinterpret_cast<float4*>(&yr[64 + tx * 4]) =
                make_float4(c_[4], c_[5], c_[6], c_[7]);
        }
    }
}

// ---------------------------------------------------------------------------
// finalize BN stats from partials -> folded scale/shift
// ---------------------------------------------------------------------------
__global__ void finalize_kernel(const float* __restrict__ gamma,
                                const float* __restrict__ beta, int layer) {
    int c = blockIdx.x;
    double s = 0.0, s2 = 0.0;
    for (int j = threadIdx.x; j < NCB; j += 256) {
        s += (double)g_psum[c][j];
        s2 += (double)g_psum2[c][j];
    }
    #pragma unroll
    for (int o = 16; o > 0; o >>= 1) {
        s += __shfl_down_sync(0xffffffffu, s, o);
        s2 += __shfl_down_sync(0xffffffffu, s2, o);
    }
    __shared__ double ws[8], ws2[8];
    int w = threadIdx.x >> 5, lane = threadIdx.x & 31;
    if (lane == 0) { ws[w] = s; ws2[w] = s2; }
    __syncthreads();
    if (threadIdx.x == 0) {
        double S = 0.0, S2 = 0.0;
        #pragma unroll
        for (int i = 0; i < 8; i++) { S += ws[i]; S2 += ws2[i]; }
        double mean = S / NCOL;
        float var = (float)(S2 / NCOL - mean * mean);
        float inv = rsqrtf(var + EPS_);
        float sc = gamma[c] * inv;
        g_scale[layer][c] = sc;
        g_shift[layer][c] = beta[c] - (float)mean * sc;
    }
}

// ---------------------------------------------------------------------------
// BN3 + ReLU over fused max/min -> new_features (B, 256, M)
// ---------------------------------------------------------------------------
__global__ void maxpool_kernel(float* __restrict__ out) {
    int idx = blockIdx.x * blockDim.x + threadIdx.x;   // 256*4096 total
    int q = idx & (NQ - 1);
    int c = idx >> 12;
    float sc = g_scale[2][c];
    float sh = g_shift[2][c];
    float v = (sc >= 0.f) ? g_max[c][q] : g_min[c][q];
    float r = fmaxf(fmaf(v, sc, sh), 0.f);
    int b = q >> 10;
    int m = q & 1023;
    out[12288 + ((size_t)b * 256 + c) * M_ + m] = r;
}

// ---------------------------------------------------------------------------
extern "C" void kernel_launch(void* const* d_in, const int* in_sizes, int n_in,
                              void* d_out, int out_size) {
    const float* xyz  = (const float*)d_in[0];
    const float* feat = (const float*)d_in[1];
    const int* indices = (const int*)d_in[2];
    const float* w1 = (const float*)d_in[3];
    const float* b1 = (const float*)d_in[4];
    const float* g1 = (const float*)d_in[5];
    const float* be1 = (const float*)d_in[6];
    const float* w2 = (const float*)d_in[7];
    const float* b2 = (const float*)d_in[8];
    const float* g2 = (const float*)d_in[9];
    const float* be2 = (const float*)d_in[10];
    const float* w3 = (const float*)d_in[11];
    const float* b3 = (const float*)d_in[12];
    const float* g3 = (const float*)d_in[13];
    const float* be3 = (const float*)d_in[14];
    float* out = (float*)d_out;

    ballquery_kernel<<<NQ / 4, 128>>>(xyz, indices, out);

    // conv1: 131 -> 128, gather fused into B loader
    gemm_kernel<0, 131, 0><<<dim3(NCB, 1), 256>>>(
        w1, b1, nullptr, xyz, feat, out, g_Y1);
    finalize_kernel<<<128, 256>>>(g1, be1, 0);
    // conv2: 128 -> 128 (BN1+ReLU on load)
    gemm_kernel<1, 128, 0><<<dim3(NCB, 1), 256>>>(
        w2, b2, g_Y1, nullptr, nullptr, nullptr, g_Y2);
    finalize_kernel<<<128, 256>>>(g2, be2, 1);
    // conv3: 128 -> 256 (BN2+ReLU on load), fused max/min, no Y write
    gemm_kernel<2, 128, 1><<<dim3(NCB, 2), 256>>>(
        w3, b3, g_Y2, nullptr, nullptr, nullptr, nullptr);
    finalize_kernel<<<256, 256>>>(g3, be3, 2);
    // BN3 + ReLU applied to max/min
    maxpool_kernel<<<(256 * NQ) / 256, 256>>>(out);
}